// round 1
// baseline (speedup 1.0000x reference)
#include <cuda_runtime.h>
#include <cstdint>

#define SEQ   64
#define CHN   256
#define SP    256      // 16*16 spatial
#define NB    512      // total frames
#define NCLIP 8

// Scratch (no allocations allowed)
__device__ float d_K[CHN * SEQ];
__device__ float d_meanC[NB * SP];
__device__ float d_rstdC[NB * SP];

// ---------------------------------------------------------------------------
// Kernel 1: K[c,tau] = sum_n B[c,n]*C[c,n]*sigmoid(A_log[c,n])^tau  (+D at tau=0)
// ---------------------------------------------------------------------------
__global__ void kern_K(const float* __restrict__ A_log, const float* __restrict__ B,
                       const float* __restrict__ C, const float* __restrict__ D) {
    int c = blockIdx.x, tau = threadIdx.x;   // 256 blocks x 64 threads
    __shared__ float sla[64], sbc[64];
    float a = 1.f / (1.f + expf(-A_log[c * 64 + tau]));
    sla[tau] = logf(a);
    sbc[tau] = B[c * 64 + tau] * C[c * 64 + tau];
    __syncthreads();
    float acc = 0.f;
    float ft = (float)tau;
    #pragma unroll 8
    for (int n = 0; n < 64; n++) acc += sbc[n] * expf(ft * sla[n]);
    if (tau == 0) acc += D[c];
    d_K[c * 64 + tau] = acc;
}

// ---------------------------------------------------------------------------
// Kernel 2: per-(frame b, pixel k) LayerNorm stats over channels (coalesced)
// ---------------------------------------------------------------------------
__global__ void __launch_bounds__(256) kern_stats(const float* __restrict__ ix) {
    int b = blockIdx.x, k = threadIdx.x;     // 512 blocks x 256 threads
    const float* p = ix + (size_t)b * (CHN * SP) + k;
    float s = 0.f, sq = 0.f;
    #pragma unroll 16
    for (int c = 0; c < CHN; c++) {
        float v = p[(size_t)c * SP];
        s += v;
        sq = fmaf(v, v, sq);
    }
    float m = s * (1.f / CHN);
    float var = fmaf(-m, m, sq * (1.f / CHN));
    d_meanC[b * SP + k] = m;
    d_rstdC[b * SP + k] = rsqrtf(var + 1e-5f);
}

// ---------------------------------------------------------------------------
// Kernel 3: fused LN -> causal conv (SSM) -> gelu*silu -> spatial LN + residual LN
// One CTA per (clip, channel). 256 threads = one per pixel.
// ---------------------------------------------------------------------------
__global__ void __launch_bounds__(256, 2) kern_main(
    const float* __restrict__ ix,
    const float* __restrict__ g_in, const float* __restrict__ b_in,
    const float* __restrict__ g1, const float* __restrict__ b1,
    const float* __restrict__ g2, const float* __restrict__ b2,
    float* __restrict__ out)
{
    extern __shared__ float smem[];
    float* sx   = smem;            // 64*256 = 16384 floats: x_ln, then reused for z
    float* sg1  = smem + 16384;    // 256
    float* sb1  = sg1 + 256;
    float* sg2  = sb1 + 256;
    float* sb2  = sg2 + 256;
    float* sK   = sb2 + 256;       // 64
    float* sIxM = sK + 64;         // 64
    float* sIxR = sIxM + 64;       // 64

    const int tid  = threadIdx.x;
    const int c    = blockIdx.x & 255;
    const int clip = blockIdx.x >> 8;
    const int w    = tid >> 5, l = tid & 31;

    sg1[tid] = g1[tid];  sb1[tid] = b1[tid];
    sg2[tid] = g2[tid];  sb2[tid] = b2[tid];
    if (tid < 64) sK[tid] = d_K[c * 64 + tid];
    const float gin = g_in[c], bin = b_in[c];

    // ---- Phase 1: load tile, apply channel-LN into smem, raw-ix spatial stats ----
    #pragma unroll
    for (int r = 0; r < 8; r++) {
        int t = w * 8 + r;
        size_t b = (size_t)(clip * 64 + t);
        const float4* prow = (const float4*)(ix + (b * CHN + c) * SP);
        const float4* pm   = (const float4*)(d_meanC + b * SP);
        const float4* pr   = (const float4*)(d_rstdC + b * SP);
        float s = 0.f, sq = 0.f;
        #pragma unroll
        for (int j = 0; j < 2; j++) {
            int k4 = l + 32 * j;
            float4 v  = prow[k4];
            float4 m4 = pm[k4];
            float4 r4 = pr[k4];
            s += v.x + v.y + v.z + v.w;
            sq = fmaf(v.x, v.x, fmaf(v.y, v.y, fmaf(v.z, v.z, fmaf(v.w, v.w, sq))));
            float4 xl;
            xl.x = (v.x - m4.x) * r4.x * gin + bin;
            xl.y = (v.y - m4.y) * r4.y * gin + bin;
            xl.z = (v.z - m4.z) * r4.z * gin + bin;
            xl.w = (v.w - m4.w) * r4.w * gin + bin;
            ((float4*)(sx + t * SP))[k4] = xl;
        }
        #pragma unroll
        for (int o = 16; o; o >>= 1) {
            s  += __shfl_xor_sync(0xffffffffu, s, o);
            sq += __shfl_xor_sync(0xffffffffu, sq, o);
        }
        if (l == 0) {
            float m = s * (1.f / SP);
            sIxM[t] = m;
            sIxR[t] = rsqrtf(fmaf(-m, m, sq * (1.f / SP)) + 1e-5f);
        }
    }
    __syncthreads();

    // ---- Phase 2: triangular causal conv, register-tiled 8x8, thread k = tid ----
    float y[64];
    #pragma unroll
    for (int i = 0; i < 64; i++) y[i] = 0.f;
    {
        const int k = tid;
        #pragma unroll
        for (int t0 = 0; t0 < 64; t0 += 8) {          // tau tile
            float kv[8];
            #pragma unroll
            for (int i = 0; i < 8; i++) kv[i] = sK[t0 + i];
            #pragma unroll
            for (int s0 = 0; s0 < 64 - t0; s0 += 8) { // s tile
                float xv[8];
                #pragma unroll
                for (int j = 0; j < 8; j++) xv[j] = sx[(s0 + j) * SP + k];
                #pragma unroll
                for (int i = 0; i < 8; i++) {
                    #pragma unroll
                    for (int j = 0; j < 8; j++) {
                        int t = s0 + j + t0 + i;
                        if (t < 64) y[t] = fmaf(kv[i], xv[j], y[t]);
                    }
                }
            }
        }
    }

    // ---- Phase 3: gelu(erf) then x*sigmoid(x); each thread owns its own column,
    //      so overwriting sx needs no sync here ----
    #pragma unroll
    for (int t = 0; t < 64; t++) {
        float v = y[t];
        float g = 0.5f * v * (1.f + erff(v * 0.70710678118f));
        float z = g / (1.f + __expf(-g));
        sx[t * SP + tid] = z;
    }
    __syncthreads();

    // ---- Phase 4: spatial LN of z + residual spatial LN of ix, write output ----
    #pragma unroll
    for (int r = 0; r < 8; r++) {
        int t = w * 8 + r;
        float4 z4[2];
        float s = 0.f, sq = 0.f;
        #pragma unroll
        for (int j = 0; j < 2; j++) {
            z4[j] = ((const float4*)(sx + t * SP))[l + 32 * j];
            s += z4[j].x + z4[j].y + z4[j].z + z4[j].w;
            sq = fmaf(z4[j].x, z4[j].x, fmaf(z4[j].y, z4[j].y,
                 fmaf(z4[j].z, z4[j].z, fmaf(z4[j].w, z4[j].w, sq))));
        }
        #pragma unroll
        for (int o = 16; o; o >>= 1) {
            s  += __shfl_xor_sync(0xffffffffu, s, o);
            sq += __shfl_xor_sync(0xffffffffu, sq, o);
        }
        float m  = s * (1.f / SP);
        float rs = rsqrtf(fmaf(-m, m, sq * (1.f / SP)) + 1e-5f);
        size_t b = (size_t)(clip * 64 + t);
        const float ixm = sIxM[t], ixr = sIxR[t];
        const float4* prow = (const float4*)(ix + (b * CHN + c) * SP);
        float4* pout = (float4*)(out + (b * CHN + c) * SP);
        #pragma unroll
        for (int j = 0; j < 2; j++) {
            int k4 = l + 32 * j;
            float4 v  = prow[k4];
            float4 G1 = ((const float4*)sg1)[k4];
            float4 B1 = ((const float4*)sb1)[k4];
            float4 G2 = ((const float4*)sg2)[k4];
            float4 B2 = ((const float4*)sb2)[k4];
            float4 o4;
            o4.x = (z4[j].x - m) * rs * G1.x + B1.x + (v.x - ixm) * ixr * G2.x + B2.x;
            o4.y = (z4[j].y - m) * rs * G1.y + B1.y + (v.y - ixm) * ixr * G2.y + B2.y;
            o4.z = (z4[j].z - m) * rs * G1.z + B1.z + (v.z - ixm) * ixr * G2.z + B2.z;
            o4.w = (z4[j].w - m) * rs * G1.w + B1.w + (v.w - ixm) * ixr * G2.w + B2.w;
            pout[k4] = o4;
        }
    }
}

// ---------------------------------------------------------------------------
extern "C" void kernel_launch(void* const* d_in, const int* in_sizes, int n_in,
                              void* d_out, int out_size) {
    const float* ix    = (const float*)d_in[0];
    const float* A_log = (const float*)d_in[1];
    const float* B     = (const float*)d_in[2];
    const float* C     = (const float*)d_in[3];
    const float* D     = (const float*)d_in[4];
    const float* g_in  = (const float*)d_in[5];
    const float* b_in  = (const float*)d_in[6];
    const float* g1    = (const float*)d_in[7];
    const float* b1    = (const float*)d_in[8];
    const float* g2    = (const float*)d_in[9];
    const float* b2    = (const float*)d_in[10];
    float* out = (float*)d_out;

    const int smem_bytes = (16384 + 4 * 256 + 64 + 128) * 4;  // 70400
    cudaFuncSetAttribute(kern_main, cudaFuncAttributeMaxDynamicSharedMemorySize, smem_bytes);

    kern_K<<<256, 64>>>(A_log, B, C, D);
    kern_stats<<<512, 256>>>(ix);
    kern_main<<<NCLIP * CHN, 256, smem_bytes>>>(ix, g_in, b_in, g1, b1, g2, b2, out);
}

// round 2
// speedup vs baseline: 1.2383x; 1.2383x over previous
#include <cuda_runtime.h>
#include <cstdint>

#define SEQ   64
#define CHN   256
#define SP    256      // 16*16 spatial
#define NB    512      // total frames
#define NCLIP 8
#define STR   264      // padded smem row stride (floats): (8m+g)%32 distinct -> conflict-free B frags

// Scratch (no allocations allowed)
__device__ float d_K[CHN * SEQ];
__device__ float d_meanC[NB * SP];
__device__ float d_rstdC[NB * SP];

// ---------------------------------------------------------------------------
// Kernel 1: K[c,tau] = sum_n B[c,n]*C[c,n]*sigmoid(A_log[c,n])^tau  (+D at tau=0)
// ---------------------------------------------------------------------------
__global__ void kern_K(const float* __restrict__ A_log, const float* __restrict__ B,
                       const float* __restrict__ C, const float* __restrict__ D) {
    int c = blockIdx.x, tau = threadIdx.x;   // 256 blocks x 64 threads
    __shared__ float sla[64], sbc[64];
    float a = 1.f / (1.f + expf(-A_log[c * 64 + tau]));
    sla[tau] = logf(a);
    sbc[tau] = B[c * 64 + tau] * C[c * 64 + tau];
    __syncthreads();
    float acc = 0.f;
    float ft = (float)tau;
    #pragma unroll 8
    for (int n = 0; n < 64; n++) acc += sbc[n] * expf(ft * sla[n]);
    if (tau == 0) acc += D[c];
    d_K[c * 64 + tau] = acc;
}

// ---------------------------------------------------------------------------
// Kernel 2: per-(frame b, pixel k) LayerNorm stats over channels (coalesced)
// ---------------------------------------------------------------------------
__global__ void __launch_bounds__(256) kern_stats(const float* __restrict__ ix) {
    int b = blockIdx.x, k = threadIdx.x;     // 512 blocks x 256 threads
    const float* p = ix + (size_t)b * (CHN * SP) + k;
    float s = 0.f, sq = 0.f;
    #pragma unroll 16
    for (int c = 0; c < CHN; c++) {
        float v = p[(size_t)c * SP];
        s += v;
        sq = fmaf(v, v, sq);
    }
    float m = s * (1.f / CHN);
    float var = fmaf(-m, m, sq * (1.f / CHN));
    d_meanC[b * SP + k] = m;
    d_rstdC[b * SP + k] = rsqrtf(var + 1e-5f);
}

// ---------------------------------------------------------------------------
// Helpers
// ---------------------------------------------------------------------------
__device__ __forceinline__ uint32_t f2tf32(float x) {
    uint32_t r;
    asm("cvt.rna.tf32.f32 %0, %1;" : "=r"(r) : "f"(x));
    return r;
}

__device__ __forceinline__ void mma_tf32(float* c, uint32_t a0, uint32_t a1,
                                         uint32_t a2, uint32_t a3,
                                         uint32_t b0, uint32_t b1) {
    asm volatile(
        "mma.sync.aligned.m16n8k8.row.col.f32.tf32.tf32.f32 "
        "{%0,%1,%2,%3}, {%4,%5,%6,%7}, {%8,%9}, {%0,%1,%2,%3};"
        : "+f"(c[0]), "+f"(c[1]), "+f"(c[2]), "+f"(c[3])
        : "r"(a0), "r"(a1), "r"(a2), "r"(a3), "r"(b0), "r"(b1));
}

// gelu(erf, A&S 7.1.26, |err|<=1.5e-7) followed by silu
__device__ __forceinline__ float act(float v) {
    float u  = v * 0.70710678118f;
    float au = fabsf(u);
    float t  = __fdividef(1.f, fmaf(0.3275911f, au, 1.f));
    float p  = t * fmaf(t, fmaf(t, fmaf(t, fmaf(t, 1.061405429f, -1.453152027f),
                                        1.421413741f), -0.284496736f), 0.254829592f);
    float e  = __expf(-u * u);
    float er = copysignf(fmaf(-p, e, 1.f), u);
    float g  = 0.5f * v * (1.f + er);
    return __fdividef(g, 1.f + __expf(-g));
}

// ---------------------------------------------------------------------------
// Kernel 3: fused LN -> tf32-MMA causal conv -> act -> spatial LN + residual LN
// One CTA per (clip, channel). 256 threads = 8 warps.
// Warp w: rows [16*(w&3), 16*(w&3)+16), cols [128*(w>>2), +128)
// ---------------------------------------------------------------------------
__global__ void __launch_bounds__(256, 2) kern_main(
    const float* __restrict__ ix,
    const float* __restrict__ g_in, const float* __restrict__ b_in,
    const float* __restrict__ g1, const float* __restrict__ b1,
    const float* __restrict__ g2, const float* __restrict__ b2,
    float* __restrict__ out)
{
    extern __shared__ float smem[];
    float* sx    = smem;                 // 64*264 = 16896 floats
    float* sg1   = sx + 64 * STR;        // 256
    float* sb1   = sg1 + 256;
    float* sg2   = sb1 + 256;
    float* sb2   = sg2 + 256;
    float* sK    = sb2 + 256;            // 64
    float* sIxM  = sK + 64;              // 64
    float* sIxR  = sIxM + 64;            // 64
    float* sredS = sIxR + 64;            // 128 (row x half)
    float* sredQ = sredS + 128;          // 128

    const int tid  = threadIdx.x;
    const int c    = blockIdx.x & 255;
    const int clip = blockIdx.x >> 8;
    const int w    = tid >> 5, l = tid & 31;
    const int g    = l >> 2, m = l & 3;      // mma lane decomposition
    const int mw   = w & 3, h = w >> 2;      // row-block / col-half

    sg1[tid] = g1[tid];  sb1[tid] = b1[tid];
    sg2[tid] = g2[tid];  sb2[tid] = b2[tid];
    if (tid < 64) sK[tid] = d_K[c * 64 + tid];
    const float gin = g_in[c], bin = b_in[c];

    // ---- Phase 1: load tile, apply channel-LN into smem, raw-ix spatial stats ----
    #pragma unroll
    for (int r = 0; r < 8; r++) {
        int t = w * 8 + r;
        size_t b = (size_t)(clip * 64 + t);
        const float4* prow = (const float4*)(ix + (b * CHN + c) * SP);
        const float4* pm   = (const float4*)(d_meanC + b * SP);
        const float4* pr   = (const float4*)(d_rstdC + b * SP);
        float s = 0.f, sq = 0.f;
        #pragma unroll
        for (int j = 0; j < 2; j++) {
            int k4 = l + 32 * j;
            float4 v  = prow[k4];
            float4 m4 = pm[k4];
            float4 r4 = pr[k4];
            s += v.x + v.y + v.z + v.w;
            sq = fmaf(v.x, v.x, fmaf(v.y, v.y, fmaf(v.z, v.z, fmaf(v.w, v.w, sq))));
            float4 xl;
            xl.x = (v.x - m4.x) * r4.x * gin + bin;
            xl.y = (v.y - m4.y) * r4.y * gin + bin;
            xl.z = (v.z - m4.z) * r4.z * gin + bin;
            xl.w = (v.w - m4.w) * r4.w * gin + bin;
            ((float4*)(sx + t * STR))[k4] = xl;
        }
        #pragma unroll
        for (int o = 16; o; o >>= 1) {
            s  += __shfl_xor_sync(0xffffffffu, s, o);
            sq += __shfl_xor_sync(0xffffffffu, sq, o);
        }
        if (l == 0) {
            float mm = s * (1.f / SP);
            sIxM[t] = mm;
            sIxR[t] = rsqrtf(fmaf(-mm, mm, sq * (1.f / SP)) + 1e-5f);
        }
    }
    __syncthreads();

    // ---- Phase 2: Y = L @ X via tf32 mma, 3xTF32 split precision ----
    const int r0 = 16 * mw + g;     // this thread's two output rows: r0, r0+8
    const int KB = 128 * h;         // this warp's column base

    float acc[64];
    #pragma unroll
    for (int i = 0; i < 64; i++) acc[i] = 0.f;

    #pragma unroll
    for (int ks = 0; ks < 8; ks++) {
        const int sb = 8 * ks;
        // A fragment: L[row, col] = (row>=col) ? K[row-col] : 0
        const int col0 = sb + m, col1 = sb + m + 4;
        int d0 = r0 - col0, d1 = r0 + 8 - col0, d2 = r0 - col1, d3 = r0 + 8 - col1;
        float a0f = (d0 >= 0) ? sK[d0] : 0.f;
        float a1f = (d1 >= 0) ? sK[d1] : 0.f;
        float a2f = (d2 >= 0) ? sK[d2] : 0.f;
        float a3f = (d3 >= 0) ? sK[d3] : 0.f;
        uint32_t a0h = f2tf32(a0f), a1h = f2tf32(a1f), a2h = f2tf32(a2f), a3h = f2tf32(a3f);
        uint32_t a0l = f2tf32(a0f - __uint_as_float(a0h));
        uint32_t a1l = f2tf32(a1f - __uint_as_float(a1h));
        uint32_t a2l = f2tf32(a2f - __uint_as_float(a2h));
        uint32_t a3l = f2tf32(a3f - __uint_as_float(a3h));

        const float* bp = sx + (sb + m) * STR + KB + g;  // B[row=sb+m, col=KB+g]
        #pragma unroll
        for (int nt = 0; nt < 16; nt++) {
            float b0f = bp[8 * nt];
            float b1f = bp[4 * STR + 8 * nt];
            uint32_t b0h = f2tf32(b0f), b1h = f2tf32(b1f);
            uint32_t b0l = f2tf32(b0f - __uint_as_float(b0h));
            uint32_t b1l = f2tf32(b1f - __uint_as_float(b1h));
            float* cc = acc + 4 * nt;
            mma_tf32(cc, a0h, a1h, a2h, a3h, b0h, b1h);
            mma_tf32(cc, a0h, a1h, a2h, a3h, b0l, b1l);
            mma_tf32(cc, a0l, a1l, a2l, a3l, b0h, b1h);
        }
    }

    // ---- Phase 3: gelu(erf) * sigmoid, in registers ----
    #pragma unroll
    for (int i = 0; i < 64; i++) acc[i] = act(acc[i]);

    // ---- Phase 4a: spatial-LN stats for z (rows r0, r0+8) ----
    float s0 = 0.f, q0 = 0.f, s1 = 0.f, q1 = 0.f;
    #pragma unroll
    for (int nt = 0; nt < 16; nt++) {
        s0 += acc[4 * nt] + acc[4 * nt + 1];
        q0 = fmaf(acc[4 * nt], acc[4 * nt], fmaf(acc[4 * nt + 1], acc[4 * nt + 1], q0));
        s1 += acc[4 * nt + 2] + acc[4 * nt + 3];
        q1 = fmaf(acc[4 * nt + 2], acc[4 * nt + 2], fmaf(acc[4 * nt + 3], acc[4 * nt + 3], q1));
    }
    #pragma unroll
    for (int o = 1; o <= 2; o <<= 1) {   // reduce over the 4 lanes sharing a row (lane%4)
        s0 += __shfl_xor_sync(0xffffffffu, s0, o);
        q0 += __shfl_xor_sync(0xffffffffu, q0, o);
        s1 += __shfl_xor_sync(0xffffffffu, s1, o);
        q1 += __shfl_xor_sync(0xffffffffu, q1, o);
    }
    if (m == 0) {
        sredS[2 * r0 + h] = s0;       sredQ[2 * r0 + h] = q0;
        sredS[2 * (r0 + 8) + h] = s1; sredQ[2 * (r0 + 8) + h] = q1;
    }
    __syncthreads();

    float mean0 = (sredS[2 * r0] + sredS[2 * r0 + 1]) * (1.f / SP);
    float rs0 = rsqrtf(fmaf(-mean0, mean0,
                 (sredQ[2 * r0] + sredQ[2 * r0 + 1]) * (1.f / SP)) + 1e-5f);
    float mean1 = (sredS[2 * (r0 + 8)] + sredS[2 * (r0 + 8) + 1]) * (1.f / SP);
    float rs1 = rsqrtf(fmaf(-mean1, mean1,
                 (sredQ[2 * (r0 + 8)] + sredQ[2 * (r0 + 8) + 1]) * (1.f / SP)) + 1e-5f);

    const float ixm0 = sIxM[r0],     ixr0 = sIxR[r0];
    const float ixm1 = sIxM[r0 + 8], ixr1 = sIxR[r0 + 8];
    const size_t base0 = ((size_t)(clip * 64 + r0) * CHN + c) * SP;
    const size_t base1 = ((size_t)(clip * 64 + r0 + 8) * CHN + c) * SP;

    // ---- Phase 4b: normalize + residual LN + store (float2, full 32B sectors) ----
    #pragma unroll
    for (int nt = 0; nt < 16; nt++) {
        int kc = KB + 8 * nt + 2 * m;
        float2 G1 = *(const float2*)(sg1 + kc);
        float2 B1 = *(const float2*)(sb1 + kc);
        float2 G2 = *(const float2*)(sg2 + kc);
        float2 B2 = *(const float2*)(sb2 + kc);
        float2 v0 = *(const float2*)(ix + base0 + kc);
        float2 v1 = *(const float2*)(ix + base1 + kc);
        float2 o0, o1;
        o0.x = (acc[4*nt+0] - mean0) * rs0 * G1.x + B1.x + (v0.x - ixm0) * ixr0 * G2.x + B2.x;
        o0.y = (acc[4*nt+1] - mean0) * rs0 * G1.y + B1.y + (v0.y - ixm0) * ixr0 * G2.y + B2.y;
        o1.x = (acc[4*nt+2] - mean1) * rs1 * G1.x + B1.x + (v1.x - ixm1) * ixr1 * G2.x + B2.x;
        o1.y = (acc[4*nt+3] - mean1) * rs1 * G1.y + B1.y + (v1.y - ixm1) * ixr1 * G2.y + B2.y;
        *(float2*)(out + base0 + kc) = o0;
        *(float2*)(out + base1 + kc) = o1;
    }
}

// ---------------------------------------------------------------------------
extern "C" void kernel_launch(void* const* d_in, const int* in_sizes, int n_in,
                              void* d_out, int out_size) {
    const float* ix    = (const float*)d_in[0];
    const float* A_log = (const float*)d_in[1];
    const float* B     = (const float*)d_in[2];
    const float* C     = (const float*)d_in[3];
    const float* D     = (const float*)d_in[4];
    const float* g_in  = (const float*)d_in[5];
    const float* b_in  = (const float*)d_in[6];
    const float* g1    = (const float*)d_in[7];
    const float* b1    = (const float*)d_in[8];
    const float* g2    = (const float*)d_in[9];
    const float* b2    = (const float*)d_in[10];
    float* out = (float*)d_out;

    const int smem_bytes = (64 * STR + 4 * 256 + 64 + 64 + 64 + 256) * 4;  // 73472
    cudaFuncSetAttribute(kern_main, cudaFuncAttributeMaxDynamicSharedMemorySize, smem_bytes);

    kern_K<<<256, 64>>>(A_log, B, C, D);
    kern_stats<<<512, 256>>>(ix);
    kern_main<<<NCLIP * CHN, 256, smem_bytes>>>(ix, g_in, b_in, g1, b1, g2, b2, out);
}